// round 4
// baseline (speedup 1.0000x reference)
#include <cuda_runtime.h>
#include <math.h>

#define B_   32
#define S_   4096
#define H_   768
#define D_   192
#define NS   15
#define NP   16

#define CHUNKS    32            // token chunks per batch
#define TOKCHUNK  128           // tokens per chunk
#define SUBTILES  4             // 32-token subtiles per chunk

#define INV_SCALE 0.072168783648703220563f   // 1/sqrt(192)
#define LOG_S     8.3177661667193433f        // log(4096)

#define QK_STRIDE 772           // floats per qk row in smem (/4 = 193, odd)
#define XS_STRIDE 776           // floats per x row in smem  (/4 = 194)

// smem layout (floats)
#define SM_QK   0
#define SM_XS   (16 * QK_STRIDE)                  // 12352
#define SM_WS   (SM_XS + 32 * XS_STRIDE)          // 37184 (8B aligned)
#define SM_ZS   (SM_WS + 1024)
#define SM_TOTAL_F (SM_ZS + 32)
#define SMEM_BYTES (SM_TOTAL_F * 4)               // 152,960 B

// ------------------------------------------------------------------
// device scratch
// ------------------------------------------------------------------
__device__ float g_qk[NP * H_];                       // folded queries (scaled)
__device__ float g_qb[NP];                            // q.bk (scaled)
__device__ float g_Z[B_ * NP];
__device__ float g_L[B_ * NP];
__device__ float g_Tp[(size_t)B_ * CHUNKS * NP * H_]; // partial weighted sums (50MB)
__device__ float g_sep[4 * B_ * NP * D_];             // K-split partial signal embeds

// packed f32x2 FMA
__device__ __forceinline__ float2 ffma2(float2 a, float2 b, float2 c) {
    float2 d;
    asm("fma.rn.f32x2 %0, %1, %2, %3;"
        : "=l"(reinterpret_cast<unsigned long long&>(d))
        : "l"(reinterpret_cast<unsigned long long&>(a)),
          "l"(reinterpret_cast<unsigned long long&>(b)),
          "l"(reinterpret_cast<unsigned long long&>(c)));
    return d;
}

// ------------------------------------------------------------------
// prep: g_qk[n][h] = (Wk @ q_n)[h]/sqrt(d), g_qb, zero Z/L
// ------------------------------------------------------------------
__global__ void prep_kernel(const float* __restrict__ SQ,
                            const float* __restrict__ Wk,
                            const float* __restrict__ bk) {
    int idx = blockIdx.x * 256 + threadIdx.x;   // 0..12287
    int h = idx >> 4, n = idx & 15;
    float v = 0.f;
    if (n < NS) {
        float s = 0.f;
        const float* q = SQ + n * D_;
        const float* w = Wk + h * D_;
#pragma unroll 8
        for (int d = 0; d < D_; d++) s += q[d] * w[d];
        v = s * INV_SCALE;
    }
    g_qk[n * H_ + h] = v;
    if (idx < NP) {
        float s = 0.f;
        if (idx < NS) {
            const float* q = SQ + idx * D_;
            for (int d = 0; d < D_; d++) s += q[d] * bk[d];
        }
        g_qb[idx] = s * INV_SCALE;
    }
    if (idx < B_ * NP) { g_Z[idx] = 0.f; g_L[idx] = 0.f; }
}

// ------------------------------------------------------------------
// fused pass: logits + softmax stats + weighted-x accumulation,
// single read of X. grid (CHUNKS, B), 384 threads.
// ------------------------------------------------------------------
__global__ __launch_bounds__(384, 1) void fused_pass(const float* __restrict__ X) {
    extern __shared__ float sm[];
    float*  qks = sm + SM_QK;
    float*  xs  = sm + SM_XS;
    float2* ws2 = (float2*)(sm + SM_WS);   // [16][32] packed {w,w}
    float*  zs  = sm + SM_ZS;
    float*  ls  = zs + 16;

    const int b   = blockIdx.y;
    const int cx  = blockIdx.x;
    const int tid = threadIdx.x;

    // stage qk tile once (padded rows)
    for (int i = tid; i < NP * H_; i += 384) {
        int n = i / H_, h = i - n * H_;
        qks[n * QK_STRIDE + h] = g_qk[i];
    }
    if (tid < 16) { zs[tid] = 0.f; ls[tid] = 0.f; }

    // phase-1 identity (threads 0..255): 2 tokens, 1 signal slot
    const int n1 = tid & 15;
    const int tA = tid >> 4;              // 0..15
    float qb = 0.f, zp = 0.f, lp = 0.f;
    if (tid < 256) qb = g_qb[n1];

    // phase-2 identity: 4 signals x 8 h (as 4 strided float2)
    const int ng = tid / 96;              // 0..3  -> signals ng*4..ng*4+3
    const int hg = tid - ng * 96;         // 0..95 -> float2 lanes hg + 96j

    float2 acc[4][4];
#pragma unroll
    for (int jn = 0; jn < 4; jn++)
#pragma unroll
        for (int j = 0; j < 4; j++) acc[jn][j] = make_float2(0.f, 0.f);

    const float4* xg_base =
        (const float4*)(X + (size_t)(b * S_ + cx * TOKCHUNK) * H_);

    for (int st = 0; st < SUBTILES; st++) {
        __syncthreads();   // xs free (prior phase-2 done)

        // stage 32 tokens x 768 floats, float4-coalesced
        const float4* xg = xg_base + (size_t)st * 32 * 192;
        float4* xs4 = (float4*)xs;
#pragma unroll
        for (int i = tid; i < 32 * 192; i += 384) {
            int tok = i / 192, c4 = i - tok * 192;
            xs4[tok * (XS_STRIDE / 4) + c4] = xg[tok * 192 + c4];
        }
        __syncthreads();

        // ---- phase 1: logits + exp ----
        if (tid < 256) {
            const float4* q4  = (const float4*)(qks + n1 * QK_STRIDE);
            const float4* xa4 = (const float4*)(xs + tA * XS_STRIDE);
            const float4* xb4 = (const float4*)(xs + (tA + 16) * XS_STRIDE);
            float2 aA = make_float2(0.f, 0.f), aB = make_float2(0.f, 0.f);
#pragma unroll 4
            for (int h4 = 0; h4 < 192; h4++) {
                float4 q  = q4[h4];
                float4 xa = xa4[h4];
                float4 xb = xb4[h4];
                aA = ffma2(make_float2(xa.x, xa.y), make_float2(q.x, q.y), aA);
                aA = ffma2(make_float2(xa.z, xa.w), make_float2(q.z, q.w), aA);
                aB = ffma2(make_float2(xb.x, xb.y), make_float2(q.x, q.y), aB);
                aB = ffma2(make_float2(xb.z, xb.w), make_float2(q.z, q.w), aB);
            }
            float lA = aA.x + aA.y + qb;
            float lB = aB.x + aB.y + qb;
            float wA = __expf(lA);
            float wB = __expf(lB);
            zp += wA + wB;
            lp += wA * lA + wB * lB;
            ws2[n1 * 32 + tA]      = make_float2(wA, wA);
            ws2[n1 * 32 + tA + 16] = make_float2(wB, wB);
        }
        __syncthreads();

        // ---- phase 2: T += w * x (4n x 4 float2 register tile) ----
        const float2* xs2 = (const float2*)xs;
#pragma unroll 2
        for (int tok = 0; tok < 32; tok++) {
            const float2* xr = xs2 + tok * (XS_STRIDE / 2);
            float2 xv0 = xr[hg];
            float2 xv1 = xr[hg + 96];
            float2 xv2 = xr[hg + 192];
            float2 xv3 = xr[hg + 288];
#pragma unroll
            for (int jn = 0; jn < 4; jn++) {
                float2 w2 = ws2[(ng * 4 + jn) * 32 + tok];
                acc[jn][0] = ffma2(w2, xv0, acc[jn][0]);
                acc[jn][1] = ffma2(w2, xv1, acc[jn][1]);
                acc[jn][2] = ffma2(w2, xv2, acc[jn][2]);
                acc[jn][3] = ffma2(w2, xv3, acc[jn][3]);
            }
        }
    }

    // reduce Z/L
    if (tid < 256) { atomicAdd(&zs[n1], zp); atomicAdd(&ls[n1], lp); }
    __syncthreads();
    if (tid < 16) {
        atomicAdd(&g_Z[b * NP + tid], zs[tid]);
        atomicAdd(&g_L[b * NP + tid], ls[tid]);
    }

    // write T partials
#pragma unroll
    for (int jn = 0; jn < 4; jn++) {
        int n = ng * 4 + jn;
        size_t base = (((size_t)(b * CHUNKS + cx) * NP) + n) * H_;
#pragma unroll
        for (int j = 0; j < 4; j++) {
            *(float2*)&g_Tp[base + 2 * hg + 192 * j] = acc[jn][j];
        }
    }
}

// ------------------------------------------------------------------
// R2: partial signal embeds  se_part[kc][b][n][d] = sum_{h in kc} t*Wv
// grid (NS, 4), 192 threads. t = (sum of chunk partials)/Z staged transposed.
// ------------------------------------------------------------------
__global__ __launch_bounds__(192) void r2_kernel(const float* __restrict__ Wv) {
    __shared__ float ts[192 * 34];        // [hh][b], stride 34
    __shared__ float invz[32];
    const int n = blockIdx.x, kc = blockIdx.y, tid = threadIdx.x;

    if (tid < 32) invz[tid] = 1.0f / g_Z[tid * NP + n];
    __syncthreads();

    for (int i = tid; i < 32 * 192; i += 192) {
        int bb = i / 192, hh = i - bb * 192;
        float s = 0.f;
#pragma unroll 8
        for (int c = 0; c < CHUNKS; c++)
            s += g_Tp[(((size_t)(bb * CHUNKS + c) * NP) + n) * H_ + kc * 192 + hh];
        ts[hh * 34 + bb] = s * invz[bb];
    }
    __syncthreads();

    float2 acc[16];
#pragma unroll
    for (int p = 0; p < 16; p++) acc[p] = make_float2(0.f, 0.f);

    const float* wcol = Wv + (size_t)kc * 192 * D_ + tid;
    for (int hh = 0; hh < 192; hh++) {
        float wv = wcol[(size_t)hh * D_];
        float2 wv2 = make_float2(wv, wv);
        const float2* tr = (const float2*)(ts + hh * 34);
#pragma unroll
        for (int p = 0; p < 16; p++) acc[p] = ffma2(tr[p], wv2, acc[p]);
    }
#pragma unroll
    for (int p = 0; p < 16; p++) {
        g_sep[((kc * B_ + 2 * p) * NP + n) * D_ + tid]     = acc[p].x;
        g_sep[((kc * B_ + 2 * p + 1) * NP + n) * D_ + tid] = acc[p].y;
    }
}

// ------------------------------------------------------------------
// R3: MLP head + strength. grid (NS, B), 192 threads.
// ------------------------------------------------------------------
__global__ __launch_bounds__(192) void r3_kernel(
    const float* __restrict__ bv, const float* __restrict__ NE,
    const float* __restrict__ W1, const float* __restrict__ b1,
    const float* __restrict__ W2, const float* __restrict__ b2,
    float* __restrict__ out) {
    __shared__ float eff[2 * D_];
    __shared__ float red[2];
    const int n = blockIdx.x, b = blockIdx.y, tid = threadIdx.x;

    {
        float s = bv[tid];
#pragma unroll
        for (int kc = 0; kc < 4; kc++)
            s += g_sep[((kc * B_ + b) * NP + n) * D_ + tid];
        eff[tid] = s;
        eff[D_ + tid] = NE[(size_t)n * H_ + tid];   // null_proj = first D cols
    }
    __syncthreads();

    float val = 0.f;
    if (tid < 64) {
        float h = b1[tid];
#pragma unroll 4
        for (int i = 0; i < 2 * D_; i++)
            h = fmaf(eff[i], W1[i * 64 + tid], h);
        float g = 0.5f * h * (1.0f + erff(h * 0.70710678118654752f));
        val = g * W2[tid];
    }
#pragma unroll
    for (int o = 16; o; o >>= 1) val += __shfl_xor_sync(0xffffffffu, val, o);
    if (tid < 64 && (tid & 31) == 0) red[tid >> 5] = val;
    if (tid == 64) {
        float Z = g_Z[b * NP + n], L = g_L[b * NP + n];
        float ent = logf(Z) - L / Z;
        out[b * (2 * NS) + NS + n] = 1.0f - ent * (1.0f / LOG_S);
    }
    __syncthreads();
    if (tid == 0) out[b * (2 * NS) + n] = red[0] + red[1] + b2[0];
}

// ------------------------------------------------------------------
extern "C" void kernel_launch(void* const* d_in, const int* in_sizes, int n_in,
                              void* d_out, int out_size) {
    const float* X   = (const float*)d_in[0];   // [32,4096,768]
    const float* Wk  = (const float*)d_in[1];   // [768,192]
    const float* bk  = (const float*)d_in[2];   // [192]
    const float* Wv  = (const float*)d_in[3];   // [768,192]
    const float* bv  = (const float*)d_in[4];   // [192]
    const float* SQ  = (const float*)d_in[5];   // [15,192]
    const float* NE  = (const float*)d_in[6];   // [15,768]
    const float* W1  = (const float*)d_in[7];   // [384,64]
    const float* b1  = (const float*)d_in[8];   // [64]
    const float* W2  = (const float*)d_in[9];   // [64,1]
    const float* b2  = (const float*)d_in[10];  // [1]
    float* out = (float*)d_out;                 // [32,30]

    cudaFuncSetAttribute(fused_pass,
                         cudaFuncAttributeMaxDynamicSharedMemorySize, SMEM_BYTES);

    prep_kernel<<<48, 256>>>(SQ, Wk, bk);
    fused_pass<<<dim3(CHUNKS, B_), 384, SMEM_BYTES>>>(X);
    r2_kernel<<<dim3(NS, 4), 192>>>(Wv);
    r3_kernel<<<dim3(NS, B_), 192>>>(bv, NE, W1, b1, W2, b2, out);
}

// round 6
// speedup vs baseline: 1.4693x; 1.4693x over previous
#include <cuda_runtime.h>
#include <stdint.h>
#include <math.h>

#define B_   32
#define S_   4096
#define H_   768
#define D_   192
#define NS   15
#define NP   16
#define SCB  16                 // pass_b s-chunks (Tp partials)

#define INV_SCALE 0.072168783648703220563f   // 1/sqrt(192)
#define LOG_S     8.3177661667193433f        // log(4096)

// ------------------------------------------------------------------
// device scratch
// ------------------------------------------------------------------
__device__ float g_qk[NP * H_];                         // folded queries (scaled)
__device__ float g_qb[NP];
__device__ float g_Z[B_ * NP];
__device__ float g_L[B_ * NP];
__device__ float g_w[(size_t)B_ * NS * S_];             // exp(logit)
__device__ float g_Tp[(size_t)B_ * SCB * NS * H_];      // partial weighted sums
__device__ float g_sep[4 * B_ * NS * D_];               // K-split signal embeds

// packed f32x2 FMA
__device__ __forceinline__ float2 ffma2(float2 a, float2 b, float2 c) {
    float2 d;
    asm("fma.rn.f32x2 %0, %1, %2, %3;"
        : "=l"(reinterpret_cast<unsigned long long&>(d))
        : "l"(reinterpret_cast<unsigned long long&>(a)),
          "l"(reinterpret_cast<unsigned long long&>(b)),
          "l"(reinterpret_cast<unsigned long long&>(c)));
    return d;
}

__device__ __forceinline__ void cp_async16(unsigned int saddr, const void* gaddr) {
    asm volatile("cp.async.cg.shared.global [%0], [%1], 16;" :: "r"(saddr), "l"(gaddr));
}
__device__ __forceinline__ void cp_async8(unsigned int saddr, const void* gaddr) {
    asm volatile("cp.async.ca.shared.global [%0], [%1], 8;" :: "r"(saddr), "l"(gaddr));
}
#define CP_COMMIT()  asm volatile("cp.async.commit_group;")
#define CP_WAIT(N)   asm volatile("cp.async.wait_group %0;" :: "n"(N))

// ------------------------------------------------------------------
// prep: g_qk[n][h] = (Wk @ q_n)[h]/sqrt(d), g_qb; zero Z/L
// ------------------------------------------------------------------
__global__ void prep_kernel(const float* __restrict__ SQ,
                            const float* __restrict__ Wk,
                            const float* __restrict__ bk) {
    int idx = blockIdx.x * 256 + threadIdx.x;   // 0..12287
    int h = idx >> 4, n = idx & 15;
    float v = 0.f;
    if (n < NS) {
        float s = 0.f;
        const float* q = SQ + n * D_;
        const float* w = Wk + h * D_;
#pragma unroll 8
        for (int d = 0; d < D_; d++) s += q[d] * w[d];
        v = s * INV_SCALE;
    }
    g_qk[n * H_ + h] = v;
    if (idx < NP) {
        float s = 0.f;
        if (idx < NS) {
            const float* q = SQ + idx * D_;
            for (int d = 0; d < D_; d++) s += q[d] * bk[d];
        }
        g_qb[idx] = s * INV_SCALE;
    }
    if (idx < B_ * NP) { g_Z[idx] = 0.f; g_L[idx] = 0.f; }
}

// ------------------------------------------------------------------
// pass A: logits + exp + Z/L. grid (32 schunks, 32 b), 128 thr.
// 128 tokens/block, h tiled in 32-chunks, cp.async double-buffered.
// Thread tile: 4 tok x 4 sig. Dynamic smem = 41216 B -> 5 CTAs/SM.
// ------------------------------------------------------------------
#define PA_XSTRIDE 36   // floats per x row  (16B-friendly, conflict-free)
#define PA_QSTRIDE 34   // floats per qk row (conflict-free for LDS.64)
#define PA_XS0 0
#define PA_XS1 (128 * PA_XSTRIDE)                 // 4608
#define PA_QK0 (2 * 128 * PA_XSTRIDE)             // 9216
#define PA_QK1 (PA_QK0 + 16 * PA_QSTRIDE)         // 9760
#define PA_SMEMF (PA_QK1 + 16 * PA_QSTRIDE)       // 10304 floats
#define NCH 24

__global__ __launch_bounds__(128) void pass_a(const float* __restrict__ X) {
    extern __shared__ float sm[];
    __shared__ float zs[16], ls[16];

    const int b   = blockIdx.y;
    const int s0  = blockIdx.x << 7;          // 128 tokens
    const int tid = threadIdx.x;
    const int sgrp = tid & 3;
    const int tgrp = tid >> 2;                // 0..31

    const float* xbase = X + (size_t)(b * S_ + s0) * H_;
    const unsigned int smb = (unsigned int)__cvta_generic_to_shared(sm);

    if (tid < 16) { zs[tid] = 0.f; ls[tid] = 0.f; }

    float2 acc[4][4];
#pragma unroll
    for (int i = 0; i < 4; i++)
#pragma unroll
        for (int j = 0; j < 4; j++) acc[i][j] = make_float2(0.f, 0.f);

    // prefetch chunk 0 into buffer 0
    {
        const int hc = 0;
        unsigned int xd = smb + PA_XS0 * 4;
        unsigned int qd = smb + PA_QK0 * 4;
#pragma unroll
        for (int k = 0; k < 8; k++) {
            int idx = tid + (k << 7);                 // <1024
            int tok = idx >> 3, c4 = idx & 7;
            cp_async16(xd + (tok * PA_XSTRIDE + c4 * 4) * 4,
                       xbase + (size_t)tok * H_ + hc + c4 * 4);
        }
#pragma unroll
        for (int k = 0; k < 2; k++) {
            int idx = tid + (k << 7);                 // <256
            int n = idx >> 4, c2 = idx & 15;
            cp_async8(qd + (n * PA_QSTRIDE + c2 * 2) * 4,
                      g_qk + n * H_ + hc + c2 * 2);
        }
        CP_COMMIT();
    }

    for (int c = 0; c < NCH; c++) {
        if (c + 1 < NCH) {
            const int hc = (c + 1) << 5;
            const int nb = (c + 1) & 1;
            unsigned int xd = smb + (nb ? PA_XS1 : PA_XS0) * 4;
            unsigned int qd = smb + (nb ? PA_QK1 : PA_QK0) * 4;
#pragma unroll
            for (int k = 0; k < 8; k++) {
                int idx = tid + (k << 7);
                int tok = idx >> 3, c4 = idx & 7;
                cp_async16(xd + (tok * PA_XSTRIDE + c4 * 4) * 4,
                           xbase + (size_t)tok * H_ + hc + c4 * 4);
            }
#pragma unroll
            for (int k = 0; k < 2; k++) {
                int idx = tid + (k << 7);
                int n = idx >> 4, c2 = idx & 15;
                cp_async8(qd + (n * PA_QSTRIDE + c2 * 2) * 4,
                          g_qk + n * H_ + hc + c2 * 2);
            }
            CP_COMMIT();
            CP_WAIT(1);
        } else {
            CP_WAIT(0);
        }
        __syncthreads();

        const float* xs  = sm + ((c & 1) ? PA_XS1 : PA_XS0);
        const float* qks = sm + ((c & 1) ? PA_QK1 : PA_QK0);

#pragma unroll
        for (int h2 = 0; h2 < 16; h2++) {
            float2 qv[4];
#pragma unroll
            for (int j = 0; j < 4; j++)
                qv[j] = *(const float2*)&qks[(sgrp * 4 + j) * PA_QSTRIDE + h2 * 2];
#pragma unroll
            for (int i = 0; i < 4; i++) {
                float2 xv = *(const float2*)&xs[(tgrp + (i << 5)) * PA_XSTRIDE + h2 * 2];
#pragma unroll
                for (int j = 0; j < 4; j++) acc[i][j] = ffma2(xv, qv[j], acc[i][j]);
            }
        }
        __syncthreads();   // compute done before this buffer is refilled
    }

    float qb[4];
#pragma unroll
    for (int j = 0; j < 4; j++) qb[j] = g_qb[sgrp * 4 + j];

    float zp[4] = {0.f, 0.f, 0.f, 0.f}, lp[4] = {0.f, 0.f, 0.f, 0.f};
#pragma unroll
    for (int i = 0; i < 4; i++) {
        int s = s0 + tgrp + (i << 5);
#pragma unroll
        for (int j = 0; j < 4; j++) {
            int n = sgrp * 4 + j;
            float l = acc[i][j].x + acc[i][j].y + qb[j];
            float w = __expf(l);
            zp[j] += w;
            lp[j] += w * l;
            if (n < NS) g_w[((size_t)(b * NS + n)) * S_ + s] = w;
        }
    }
#pragma unroll
    for (int j = 0; j < 4; j++) {
        atomicAdd(&zs[sgrp * 4 + j], zp[j]);
        atomicAdd(&ls[sgrp * 4 + j], lp[j]);
    }
    __syncthreads();
    if (tid < 16) {
        atomicAdd(&g_Z[b * NP + tid], zs[tid]);
        atomicAdd(&g_L[b * NP + tid], ls[tid]);
    }
}

// ------------------------------------------------------------------
// pass B: Tp[b][sc][n][h] = sum_s w*x. grid (16 sc, 32 b), 192 thr.
// Thread owns full-h float4 (tid*4). x streamed by LDG.128 inside the
// FMA loop (self-overlapping); w tiles double-buffered via cp.async.
// ------------------------------------------------------------------
__global__ __launch_bounds__(192) void pass_b(const float* __restrict__ X) {
    __shared__ float ws[2][NS * 64];

    const int sc  = blockIdx.x;
    const int b   = blockIdx.y;
    const int tid = threadIdx.x;
    const int sbeg = sc * 256;

    const unsigned int wsb = (unsigned int)__cvta_generic_to_shared(&ws[0][0]);
    const size_t wrow = (size_t)b * NS * S_;   // + n*S_ + s

    float2 acc[NS][2];
#pragma unroll
    for (int n = 0; n < NS; n++) { acc[n][0] = make_float2(0.f,0.f); acc[n][1] = make_float2(0.f,0.f); }

    // prefetch w tile 0
#pragma unroll
    for (int k = 0; k < 2; k++) {
        int idx = tid + k * 192;
        if (idx < NS * 16) {
            int n = idx >> 4, c4 = idx & 15;
            cp_async16(wsb + (n * 64 + c4 * 4) * 4,
                       g_w + wrow + (size_t)n * S_ + sbeg + c4 * 4);
        }
    }
    CP_COMMIT();

    const float* xp = X + (size_t)(b * S_ + sbeg) * H_ + tid * 4;

    for (int t = 0; t < 4; t++) {
        if (t + 1 < 4) {
            unsigned int dst = wsb + ((t + 1) & 1) * (NS * 64 * 4);
#pragma unroll
            for (int k = 0; k < 2; k++) {
                int idx = tid + k * 192;
                if (idx < NS * 16) {
                    int n = idx >> 4, c4 = idx & 15;
                    cp_async16(dst + (n * 64 + c4 * 4) * 4,
                               g_w + wrow + (size_t)n * S_ + sbeg + (t + 1) * 64 + c4 * 4);
                }
            }
            CP_COMMIT();
            CP_WAIT(1);
        } else {
            CP_WAIT(0);
        }
        __syncthreads();

        const float* wt = ws[t & 1];
#pragma unroll 4
        for (int si = 0; si < 64; si++) {
            float4 xv = *(const float4*)xp;
            xp += H_;
            float2 xlo = make_float2(xv.x, xv.y);
            float2 xhi = make_float2(xv.z, xv.w);
#pragma unroll
            for (int n = 0; n < NS; n++) {
                float w = wt[n * 64 + si];
                float2 w2 = make_float2(w, w);
                acc[n][0] = ffma2(w2, xlo, acc[n][0]);
                acc[n][1] = ffma2(w2, xhi, acc[n][1]);
            }
        }
        __syncthreads();
    }

#pragma unroll
    for (int n = 0; n < NS; n++) {
        float4 o = make_float4(acc[n][0].x, acc[n][0].y, acc[n][1].x, acc[n][1].y);
        *(float4*)&g_Tp[((size_t)(b * SCB + sc) * NS + n) * H_ + tid * 4] = o;
    }
}

// ------------------------------------------------------------------
// R2: partial signal embeds. grid (NS, 4), 192 thr.
// ------------------------------------------------------------------
__global__ __launch_bounds__(192) void r2_kernel(const float* __restrict__ Wv) {
    __shared__ float ts[192 * 34];        // [hh][b], stride 34
    __shared__ float invz[32];
    const int n = blockIdx.x, kc = blockIdx.y, tid = threadIdx.x;

    if (tid < 32) invz[tid] = 1.0f / g_Z[tid * NP + n];
    __syncthreads();

    for (int i = tid; i < 32 * 192; i += 192) {
        int bb = i / 192, hh = i - bb * 192;
        float s = 0.f;
#pragma unroll 8
        for (int c = 0; c < SCB; c++)
            s += g_Tp[((size_t)(bb * SCB + c) * NS + n) * H_ + kc * 192 + hh];
        ts[hh * 34 + bb] = s * invz[bb];
    }
    __syncthreads();

    float2 acc[16];
#pragma unroll
    for (int p = 0; p < 16; p++) acc[p] = make_float2(0.f, 0.f);

    const float* wcol = Wv + (size_t)kc * 192 * D_ + tid;
    for (int hh = 0; hh < 192; hh++) {
        float wv = wcol[(size_t)hh * D_];
        float2 wv2 = make_float2(wv, wv);
        const float2* tr = (const float2*)(ts + hh * 34);
#pragma unroll
        for (int p = 0; p < 16; p++) acc[p] = ffma2(tr[p], wv2, acc[p]);
    }
#pragma unroll
    for (int p = 0; p < 16; p++) {
        g_sep[((kc * B_ + 2 * p) * NS + n) * D_ + tid]     = acc[p].x;
        g_sep[((kc * B_ + 2 * p + 1) * NS + n) * D_ + tid] = acc[p].y;
    }
}

// ------------------------------------------------------------------
// R3: MLP head + strength. One block per batch (32 blocks, 256 thr).
// W1 staged once in smem; 960 hidden units across threads (4 chains).
// dyn smem: W1s 24576 + eff 15*384 + gh 960 floats = 125184 B
// ------------------------------------------------------------------
#define R3_W1  0
#define R3_EFF 24576
#define R3_GH  (24576 + 15 * 384)
#define R3_SMEMF (R3_GH + 960)

__global__ __launch_bounds__(256) void r3_kernel(
    const float* __restrict__ bv, const float* __restrict__ NE,
    const float* __restrict__ W1, const float* __restrict__ b1,
    const float* __restrict__ W2, const float* __restrict__ b2,
    float* __restrict__ out) {
    extern __shared__ float sm[];
    float* W1s = sm + R3_W1;
    float* eff = sm + R3_EFF;   // [15][384]
    float* gh  = sm + R3_GH;    // [960]
    const int b = blockIdx.x, tid = threadIdx.x;

    // stage W1 (float4 coalesced)
    {
        float4* d = (float4*)W1s;
        const float4* s = (const float4*)W1;
#pragma unroll
        for (int k = 0; k < 24; k++) d[tid + 256 * k] = s[tid + 256 * k];
    }
    // stage eff rows: [signal_embed (192) | null_proj (192)]
    for (int i = tid; i < NS * 384; i += 256) {
        int n = i / 384, ii = i - n * 384;
        float v;
        if (ii < D_) {
            v = bv[ii];
#pragma unroll
            for (int kc = 0; kc < 4; kc++)
                v += g_sep[((kc * B_ + b) * NS + n) * D_ + ii];
        } else {
            v = NE[(size_t)n * H_ + (ii - D_)];
        }
        eff[i] = v;
    }
    __syncthreads();

    // hidden units: u = n*64 + j, 960 total
#pragma unroll
    for (int k = 0; k < 4; k++) {
        int u = tid + 256 * k;
        if (u < NS * 64) {
            int n = u >> 6, j = u & 63;
            const float* e = eff + n * 384;
            float h = b1[j];
#pragma unroll 4
            for (int i = 0; i < 384; i++) h = fmaf(e[i], W1s[i * 64 + j], h);
            gh[u] = 0.5f * h * (1.0f + erff(h * 0.70710678118654752f));
        }
    }
    if (tid < NS) {
        float Z = g_Z[b * NP + tid], L = g_L[b * NP + tid];
        float ent = logf(Z) - L / Z;
        out[b * (2 * NS) + NS + tid] = 1.0f - ent * (1.0f / LOG_S);
    }
    __syncthreads();

    // effects: warp w handles signals 2w, 2w+1
    int wid = tid >> 5, lid = tid & 31;
#pragma unroll
    for (int r = 0; r < 2; r++) {
        int n = wid * 2 + r;
        if (n < NS) {
            float v = gh[n * 64 + lid] * W2[lid] + gh[n * 64 + lid + 32] * W2[lid + 32];
#pragma unroll
            for (int o = 16; o; o >>= 1) v += __shfl_xor_sync(0xffffffffu, v, o);
            if (lid == 0) out[b * (2 * NS) + n] = v + b2[0];
        }
    }
}

// ------------------------------------------------------------------
extern "C" void kernel_launch(void* const* d_in, const int* in_sizes, int n_in,
                              void* d_out, int out_size) {
    const float* X   = (const float*)d_in[0];   // [32,4096,768]
    const float* Wk  = (const float*)d_in[1];
    const float* bk  = (const float*)d_in[2];
    const float* Wv  = (const float*)d_in[3];
    const float* bv  = (const float*)d_in[4];
    const float* SQ  = (const float*)d_in[5];
    const float* NE  = (const float*)d_in[6];
    const float* W1  = (const float*)d_in[7];
    const float* b1  = (const float*)d_in[8];
    const float* W2  = (const float*)d_in[9];
    const float* b2  = (const float*)d_in[10];
    float* out = (float*)d_out;                 // [32,30]

    cudaFuncSetAttribute(pass_a, cudaFuncAttributeMaxDynamicSharedMemorySize,
                         PA_SMEMF * 4);
    cudaFuncSetAttribute(r3_kernel, cudaFuncAttributeMaxDynamicSharedMemorySize,
                         R3_SMEMF * 4);

    prep_kernel<<<48, 256>>>(SQ, Wk, bk);
    pass_a<<<dim3(32, B_), 128, PA_SMEMF * 4>>>(X);
    pass_b<<<dim3(SCB, B_), 192>>>(X);
    r2_kernel<<<dim3(NS, 4), 192>>>(Wv);
    r3_kernel<<<B_, 256, R3_SMEMF * 4>>>(bv, NE, W1, b1, W2, b2, out);
}

// round 7
// speedup vs baseline: 1.6296x; 1.1091x over previous
#include <cuda_runtime.h>
#include <stdint.h>
#include <math.h>

#define B_   32
#define S_   4096
#define H_   768
#define D_   192
#define NS   15
#define NP   16
#define SCB  16                 // pass_b s-chunks

#define INV_SCALE 0.072168783648703220563f   // 1/sqrt(192)
#define LOG_S     8.3177661667193433f        // log(4096)

// ------------------------------------------------------------------
// device scratch
// ------------------------------------------------------------------
__device__ float g_qk[NP * H_];                 // folded queries (scaled)
__device__ float g_qb[NP];
__device__ float g_Z[B_ * NP];
__device__ float g_L[B_ * NP];
__device__ float g_w[(size_t)B_ * NS * S_];     // exp(logit)
__device__ float g_T[B_ * NS * H_];             // dense weighted-x sums (red.add)
__device__ float g_sep[B_ * NS * D_];           // signal embeds (pre-bias)

// packed f32x2 FMA
__device__ __forceinline__ float2 ffma2(float2 a, float2 b, float2 c) {
    float2 d;
    asm("fma.rn.f32x2 %0, %1, %2, %3;"
        : "=l"(reinterpret_cast<unsigned long long&>(d))
        : "l"(reinterpret_cast<unsigned long long&>(a)),
          "l"(reinterpret_cast<unsigned long long&>(b)),
          "l"(reinterpret_cast<unsigned long long&>(c)));
    return d;
}

__device__ __forceinline__ void cp_async16(unsigned int saddr, const void* gaddr) {
    asm volatile("cp.async.cg.shared.global [%0], [%1], 16;" :: "r"(saddr), "l"(gaddr));
}
__device__ __forceinline__ void cp_async8(unsigned int saddr, const void* gaddr) {
    asm volatile("cp.async.ca.shared.global [%0], [%1], 8;" :: "r"(saddr), "l"(gaddr));
}
#define CP_COMMIT()  asm volatile("cp.async.commit_group;")
#define CP_WAIT(N)   asm volatile("cp.async.wait_group %0;" :: "n"(N))

__device__ __forceinline__ void red_add_v4(float* ptr, float a, float b, float c, float d) {
    asm volatile("red.global.add.v4.f32 [%0], {%1,%2,%3,%4};"
                 :: "l"(ptr), "f"(a), "f"(b), "f"(c), "f"(d) : "memory");
}

// ------------------------------------------------------------------
// prep: g_qk = (Wk @ q_n)/sqrt(d), g_qb; zero Z/L and g_T
// ------------------------------------------------------------------
__global__ void prep_kernel(const float* __restrict__ SQ,
                            const float* __restrict__ Wk,
                            const float* __restrict__ bk) {
    int idx = blockIdx.x * 256 + threadIdx.x;   // 0..12287
    int h = idx >> 4, n = idx & 15;
    float v = 0.f;
    if (n < NS) {
        float s = 0.f;
        const float* q = SQ + n * D_;
        const float* w = Wk + h * D_;
#pragma unroll 8
        for (int d = 0; d < D_; d++) s += q[d] * w[d];
        v = s * INV_SCALE;
    }
    g_qk[n * H_ + h] = v;
    if (idx < NP) {
        float s = 0.f;
        if (idx < NS) {
            const float* q = SQ + idx * D_;
            for (int d = 0; d < D_; d++) s += q[d] * bk[d];
        }
        g_qb[idx] = s * INV_SCALE;
    }
    if (idx < B_ * NP) { g_Z[idx] = 0.f; g_L[idx] = 0.f; }
#pragma unroll
    for (int k = 0; k < 30; k++)            // 30*12288 = 368640 = B*NS*H
        g_T[idx + k * 12288] = 0.f;
}

// ------------------------------------------------------------------
// pass A: logits + exp + Z/L. grid (32 schunks, 32 b), 128 thr.
// 128 tokens/block, h tiled in 32-chunks, cp.async double-buffered.
// ------------------------------------------------------------------
#define PA_XSTRIDE 36
#define PA_QSTRIDE 34
#define PA_XS0 0
#define PA_XS1 (128 * PA_XSTRIDE)
#define PA_QK0 (2 * 128 * PA_XSTRIDE)
#define PA_QK1 (PA_QK0 + 16 * PA_QSTRIDE)
#define PA_SMEMF (PA_QK1 + 16 * PA_QSTRIDE)
#define NCH 24

__global__ __launch_bounds__(128) void pass_a(const float* __restrict__ X) {
    extern __shared__ float sm[];
    __shared__ float zs[16], ls[16];

    const int b   = blockIdx.y;
    const int s0  = blockIdx.x << 7;
    const int tid = threadIdx.x;
    const int sgrp = tid & 3;
    const int tgrp = tid >> 2;

    const float* xbase = X + (size_t)(b * S_ + s0) * H_;
    const unsigned int smb = (unsigned int)__cvta_generic_to_shared(sm);

    if (tid < 16) { zs[tid] = 0.f; ls[tid] = 0.f; }

    float2 acc[4][4];
#pragma unroll
    for (int i = 0; i < 4; i++)
#pragma unroll
        for (int j = 0; j < 4; j++) acc[i][j] = make_float2(0.f, 0.f);

    {
        const int hc = 0;
        unsigned int xd = smb + PA_XS0 * 4;
        unsigned int qd = smb + PA_QK0 * 4;
#pragma unroll
        for (int k = 0; k < 8; k++) {
            int idx = tid + (k << 7);
            int tok = idx >> 3, c4 = idx & 7;
            cp_async16(xd + (tok * PA_XSTRIDE + c4 * 4) * 4,
                       xbase + (size_t)tok * H_ + hc + c4 * 4);
        }
#pragma unroll
        for (int k = 0; k < 2; k++) {
            int idx = tid + (k << 7);
            int n = idx >> 4, c2 = idx & 15;
            cp_async8(qd + (n * PA_QSTRIDE + c2 * 2) * 4,
                      g_qk + n * H_ + hc + c2 * 2);
        }
        CP_COMMIT();
    }

    for (int c = 0; c < NCH; c++) {
        if (c + 1 < NCH) {
            const int hc = (c + 1) << 5;
            const int nb = (c + 1) & 1;
            unsigned int xd = smb + (nb ? PA_XS1 : PA_XS0) * 4;
            unsigned int qd = smb + (nb ? PA_QK1 : PA_QK0) * 4;
#pragma unroll
            for (int k = 0; k < 8; k++) {
                int idx = tid + (k << 7);
                int tok = idx >> 3, c4 = idx & 7;
                cp_async16(xd + (tok * PA_XSTRIDE + c4 * 4) * 4,
                           xbase + (size_t)tok * H_ + hc + c4 * 4);
            }
#pragma unroll
            for (int k = 0; k < 2; k++) {
                int idx = tid + (k << 7);
                int n = idx >> 4, c2 = idx & 15;
                cp_async8(qd + (n * PA_QSTRIDE + c2 * 2) * 4,
                          g_qk + n * H_ + hc + c2 * 2);
            }
            CP_COMMIT();
            CP_WAIT(1);
        } else {
            CP_WAIT(0);
        }
        __syncthreads();

        const float* xs  = sm + ((c & 1) ? PA_XS1 : PA_XS0);
        const float* qks = sm + ((c & 1) ? PA_QK1 : PA_QK0);

#pragma unroll
        for (int h2 = 0; h2 < 16; h2++) {
            float2 qv[4];
#pragma unroll
            for (int j = 0; j < 4; j++)
                qv[j] = *(const float2*)&qks[(sgrp * 4 + j) * PA_QSTRIDE + h2 * 2];
#pragma unroll
            for (int i = 0; i < 4; i++) {
                float2 xv = *(const float2*)&xs[(tgrp + (i << 5)) * PA_XSTRIDE + h2 * 2];
#pragma unroll
                for (int j = 0; j < 4; j++) acc[i][j] = ffma2(xv, qv[j], acc[i][j]);
            }
        }
        __syncthreads();
    }

    float qb[4];
#pragma unroll
    for (int j = 0; j < 4; j++) qb[j] = g_qb[sgrp * 4 + j];

    float zp[4] = {0.f, 0.f, 0.f, 0.f}, lp[4] = {0.f, 0.f, 0.f, 0.f};
#pragma unroll
    for (int i = 0; i < 4; i++) {
        int s = s0 + tgrp + (i << 5);
#pragma unroll
        for (int j = 0; j < 4; j++) {
            int n = sgrp * 4 + j;
            float l = acc[i][j].x + acc[i][j].y + qb[j];
            float w = __expf(l);
            zp[j] += w;
            lp[j] += w * l;
            if (n < NS) g_w[((size_t)(b * NS + n)) * S_ + s] = w;
        }
    }
#pragma unroll
    for (int j = 0; j < 4; j++) {
        atomicAdd(&zs[sgrp * 4 + j], zp[j]);
        atomicAdd(&ls[sgrp * 4 + j], lp[j]);
    }
    __syncthreads();
    if (tid < 16) {
        atomicAdd(&g_Z[b * NP + tid], zs[tid]);
        atomicAdd(&g_L[b * NP + tid], ls[tid]);
    }
}

// ------------------------------------------------------------------
// pass B: g_T[b][n][h] += sum_s w*x via red.global.add.v4.
// grid (16 sc, 32 b), 192 thr. Thread owns h-float4 (tid*4).
// Inner: 4 tokens per step, w via LDS.128 (4 tokens x 1 load per n).
// ------------------------------------------------------------------
__global__ __launch_bounds__(192) void pass_b(const float* __restrict__ X) {
    __shared__ float ws[2][NS * 64];

    const int sc  = blockIdx.x;
    const int b   = blockIdx.y;
    const int tid = threadIdx.x;
    const int sbeg = sc * 256;

    const unsigned int wsb = (unsigned int)__cvta_generic_to_shared(&ws[0][0]);
    const size_t wrow = (size_t)b * NS * S_;

    float2 acc[NS][2];
#pragma unroll
    for (int n = 0; n < NS; n++) { acc[n][0] = make_float2(0.f,0.f); acc[n][1] = make_float2(0.f,0.f); }

#pragma unroll
    for (int k = 0; k < 2; k++) {
        int idx = tid + k * 192;
        if (idx < NS * 16) {
            int n = idx >> 4, c4 = idx & 15;
            cp_async16(wsb + (n * 64 + c4 * 4) * 4,
                       g_w + wrow + (size_t)n * S_ + sbeg + c4 * 4);
        }
    }
    CP_COMMIT();

    const float* xp = X + (size_t)(b * S_ + sbeg) * H_ + tid * 4;

    for (int t = 0; t < 4; t++) {
        if (t + 1 < 4) {
            unsigned int dst = wsb + ((t + 1) & 1) * (NS * 64 * 4);
#pragma unroll
            for (int k = 0; k < 2; k++) {
                int idx = tid + k * 192;
                if (idx < NS * 16) {
                    int n = idx >> 4, c4 = idx & 15;
                    cp_async16(dst + (n * 64 + c4 * 4) * 4,
                               g_w + wrow + (size_t)n * S_ + sbeg + (t + 1) * 64 + c4 * 4);
                }
            }
            CP_COMMIT();
            CP_WAIT(1);
        } else {
            CP_WAIT(0);
        }
        __syncthreads();

        const float* wt = ws[t & 1];
#pragma unroll 2
        for (int sg = 0; sg < 64; sg += 4) {
            float4 xv[4];
#pragma unroll
            for (int u = 0; u < 4; u++) { xv[u] = *(const float4*)xp; xp += H_; }
#pragma unroll
            for (int n = 0; n < NS; n++) {
                float4 w4 = *(const float4*)&wt[n * 64 + sg];
                acc[n][0] = ffma2(make_float2(w4.x, w4.x), make_float2(xv[0].x, xv[0].y), acc[n][0]);
                acc[n][1] = ffma2(make_float2(w4.x, w4.x), make_float2(xv[0].z, xv[0].w), acc[n][1]);
                acc[n][0] = ffma2(make_float2(w4.y, w4.y), make_float2(xv[1].x, xv[1].y), acc[n][0]);
                acc[n][1] = ffma2(make_float2(w4.y, w4.y), make_float2(xv[1].z, xv[1].w), acc[n][1]);
                acc[n][0] = ffma2(make_float2(w4.z, w4.z), make_float2(xv[2].x, xv[2].y), acc[n][0]);
                acc[n][1] = ffma2(make_float2(w4.z, w4.z), make_float2(xv[2].z, xv[2].w), acc[n][1]);
                acc[n][0] = ffma2(make_float2(w4.w, w4.w), make_float2(xv[3].x, xv[3].y), acc[n][0]);
                acc[n][1] = ffma2(make_float2(w4.w, w4.w), make_float2(xv[3].z, xv[3].w), acc[n][1]);
            }
        }
        __syncthreads();
    }

#pragma unroll
    for (int n = 0; n < NS; n++) {
        red_add_v4(&g_T[(b * NS + n) * H_ + tid * 4],
                   acc[n][0].x, acc[n][0].y, acc[n][1].x, acc[n][1].y);
    }
}

// ------------------------------------------------------------------
// wv_kernel: se[b][n][d] = (g_T[b][n][:]/Z) @ Wv. grid (NS, 8), 192 thr.
// 4 batches per block; t staged as ts4[hh] = {t for 4 batches}.
// ------------------------------------------------------------------
__global__ __launch_bounds__(192) void wv_kernel(const float* __restrict__ Wv) {
    __shared__ float4 ts4[H_];      // [hh] -> 4 batches
    __shared__ float invz[4];
    const int n  = blockIdx.x;
    const int bg = blockIdx.y;      // batches bg*4..bg*4+3
    const int tid = threadIdx.x;

    if (tid < 4) invz[tid] = 1.0f / g_Z[(bg * 4 + tid) * NP + n];
    __syncthreads();

    for (int i = tid; i < 4 * H_; i += 192) {
        int hh = i >> 2, bb = i & 3;
        ((float*)&ts4[hh])[bb] =
            g_T[((bg * 4 + bb) * NS + n) * H_ + hh] * invz[bb];
    }
    __syncthreads();

    float2 a01 = make_float2(0.f, 0.f), a23 = make_float2(0.f, 0.f);
    const float* wcol = Wv + tid;
#pragma unroll 4
    for (int hh = 0; hh < H_; hh++) {
        float wv = wcol[(size_t)hh * D_];
        float4 tv = ts4[hh];
        a01 = ffma2(make_float2(tv.x, tv.y), make_float2(wv, wv), a01);
        a23 = ffma2(make_float2(tv.z, tv.w), make_float2(wv, wv), a23);
    }
    g_sep[((bg * 4 + 0) * NS + n) * D_ + tid] = a01.x;
    g_sep[((bg * 4 + 1) * NS + n) * D_ + tid] = a01.y;
    g_sep[((bg * 4 + 2) * NS + n) * D_ + tid] = a23.x;
    g_sep[((bg * 4 + 3) * NS + n) * D_ + tid] = a23.y;
}

// ------------------------------------------------------------------
// R3: MLP head + strength. One block per batch (32 blocks, 256 thr).
// ------------------------------------------------------------------
#define R3_W1  0
#define R3_EFF 24576
#define R3_GH  (24576 + 15 * 384)
#define R3_SMEMF (R3_GH + 960)

__global__ __launch_bounds__(256) void r3_kernel(
    const float* __restrict__ bv, const float* __restrict__ NE,
    const float* __restrict__ W1, const float* __restrict__ b1,
    const float* __restrict__ W2, const float* __restrict__ b2,
    float* __restrict__ out) {
    extern __shared__ float sm[];
    float* W1s = sm + R3_W1;
    float* eff = sm + R3_EFF;   // [15][384]
    float* gh  = sm + R3_GH;    // [960]
    const int b = blockIdx.x, tid = threadIdx.x;

    {
        float4* d = (float4*)W1s;
        const float4* s = (const float4*)W1;
#pragma unroll
        for (int k = 0; k < 24; k++) d[tid + 256 * k] = s[tid + 256 * k];
    }
    for (int i = tid; i < NS * 384; i += 256) {
        int n = i / 384, ii = i - n * 384;
        float v;
        if (ii < D_) v = bv[ii] + g_sep[(b * NS + n) * D_ + ii];
        else         v = NE[(size_t)n * H_ + (ii - D_)];
        eff[i] = v;
    }
    __syncthreads();

#pragma unroll
    for (int k = 0; k < 4; k++) {
        int u = tid + 256 * k;
        if (u < NS * 64) {
            int n = u >> 6, j = u & 63;
            const float* e = eff + n * 384;
            float h = b1[j];
#pragma unroll 4
            for (int i = 0; i < 384; i++) h = fmaf(e[i], W1s[i * 64 + j], h);
            gh[u] = 0.5f * h * (1.0f + erff(h * 0.70710678118654752f));
        }
    }
    if (tid < NS) {
        float Z = g_Z[b * NP + tid], L = g_L[b * NP + tid];
        float ent = logf(Z) - L / Z;
        out[b * (2 * NS) + NS + tid] = 1.0f - ent * (1.0f / LOG_S);
    }
    __syncthreads();

    int wid = tid >> 5, lid = tid & 31;
#pragma unroll
    for (int r = 0; r < 2; r++) {
        int n = wid * 2 + r;
        if (n < NS) {
            float v = gh[n * 64 + lid] * W2[lid] + gh[n * 64 + lid + 32] * W2[lid + 32];
#pragma unroll
            for (int o = 16; o; o >>= 1) v += __shfl_xor_sync(0xffffffffu, v, o);
            if (lid == 0) out[b * (2 * NS) + n] = v + b2[0];
        }
    }
}

// ------------------------------------------------------------------
extern "C" void kernel_launch(void* const* d_in, const int* in_sizes, int n_in,
                              void* d_out, int out_size) {
    const float* X   = (const float*)d_in[0];
    const float* Wk  = (const float*)d_in[1];
    const float* bk  = (const float*)d_in[2];
    const float* Wv  = (const float*)d_in[3];
    const float* bv  = (const float*)d_in[4];
    const float* SQ  = (const float*)d_in[5];
    const float* NE  = (const float*)d_in[6];
    const float* W1  = (const float*)d_in[7];
    const float* b1  = (const float*)d_in[8];
    const float* W2  = (const float*)d_in[9];
    const float* b2  = (const float*)d_in[10];
    float* out = (float*)d_out;                 // [32,30]

    cudaFuncSetAttribute(pass_a, cudaFuncAttributeMaxDynamicSharedMemorySize,
                         PA_SMEMF * 4);
    cudaFuncSetAttribute(r3_kernel, cudaFuncAttributeMaxDynamicSharedMemorySize,
                         R3_SMEMF * 4);

    prep_kernel<<<48, 256>>>(SQ, Wk, bk);
    pass_a<<<dim3(32, B_), 128, PA_SMEMF * 4>>>(X);
    pass_b<<<dim3(SCB, B_), 192>>>(X);
    wv_kernel<<<dim3(NS, 8), 192>>>(Wv);
    r3_kernel<<<B_, 256, R3_SMEMF * 4>>>(bv, NE, W1, b1, W2, b2, out);
}

// round 8
// speedup vs baseline: 1.8862x; 1.1575x over previous
#include <cuda_runtime.h>
#include <stdint.h>
#include <math.h>

#define B_   32
#define S_   4096
#define H_   768
#define D_   192
#define NS   15
#define NP   16
#define SCB  16                 // pass_b s-chunks

#define INV_SCALE 0.072168783648703220563f   // 1/sqrt(192)
#define LOG_S     8.3177661667193433f        // log(4096)

// ------------------------------------------------------------------
// device scratch
// ------------------------------------------------------------------
__device__ float g_qk[NP * H_];                 // folded queries (scaled)
__device__ float g_qb[NP];
__device__ float g_Z[B_ * NP];
__device__ float g_L[B_ * NP];
__device__ float g_w[(size_t)B_ * NS * S_];     // exp(logit)
__device__ float g_T[B_ * NS * H_];             // dense weighted-x sums (red.add)
__device__ float g_sep[B_ * NS * D_];           // signal embeds (pre-bias)

// packed f32x2 FMA
__device__ __forceinline__ float2 ffma2(float2 a, float2 b, float2 c) {
    float2 d;
    asm("fma.rn.f32x2 %0, %1, %2, %3;"
        : "=l"(reinterpret_cast<unsigned long long&>(d))
        : "l"(reinterpret_cast<unsigned long long&>(a)),
          "l"(reinterpret_cast<unsigned long long&>(b)),
          "l"(reinterpret_cast<unsigned long long&>(c)));
    return d;
}

__device__ __forceinline__ void cp_async16(unsigned int saddr, const void* gaddr) {
    asm volatile("cp.async.cg.shared.global [%0], [%1], 16;" :: "r"(saddr), "l"(gaddr));
}
__device__ __forceinline__ void cp_async8(unsigned int saddr, const void* gaddr) {
    asm volatile("cp.async.ca.shared.global [%0], [%1], 8;" :: "r"(saddr), "l"(gaddr));
}
#define CP_COMMIT()  asm volatile("cp.async.commit_group;")
#define CP_WAIT(N)   asm volatile("cp.async.wait_group %0;" :: "n"(N))

__device__ __forceinline__ void red_add_v4(float* ptr, float a, float b, float c, float d) {
    asm volatile("red.global.add.v4.f32 [%0], {%1,%2,%3,%4};"
                 :: "l"(ptr), "f"(a), "f"(b), "f"(c), "f"(d) : "memory");
}

// ------------------------------------------------------------------
// prep: g_qk = (Wk @ q_n)/sqrt(d), g_qb; zero Z/L and g_T
// ------------------------------------------------------------------
__global__ void prep_kernel(const float* __restrict__ SQ,
                            const float* __restrict__ Wk,
                            const float* __restrict__ bk) {
    int idx = blockIdx.x * 256 + threadIdx.x;   // 0..12287
    int h = idx >> 4, n = idx & 15;
    float v = 0.f;
    if (n < NS) {
        float s = 0.f;
        const float* q = SQ + n * D_;
        const float* w = Wk + h * D_;
#pragma unroll 8
        for (int d = 0; d < D_; d++) s += q[d] * w[d];
        v = s * INV_SCALE;
    }
    g_qk[n * H_ + h] = v;
    if (idx < NP) {
        float s = 0.f;
        if (idx < NS) {
            const float* q = SQ + idx * D_;
            for (int d = 0; d < D_; d++) s += q[d] * bk[d];
        }
        g_qb[idx] = s * INV_SCALE;
    }
    if (idx < B_ * NP) { g_Z[idx] = 0.f; g_L[idx] = 0.f; }
#pragma unroll
    for (int k = 0; k < 30; k++)            // 30*12288 = B*NS*H
        g_T[idx + k * 12288] = 0.f;
}

// ------------------------------------------------------------------
// pass A: logits + exp + Z/L. grid (16 schunks, 32 b), 128 thr.
// 256 tokens/block, h tiled in 32-chunks, cp.async double-buffered.
// Thread tile: 8 tok x 4 sig. smem 78 KB -> 2 CTAs/SM.
// ------------------------------------------------------------------
#define PA_XSTRIDE 36
#define PA_QSTRIDE 34
#define PA_TOK 256
#define PA_XS0 0
#define PA_XS1 (PA_TOK * PA_XSTRIDE)              // 9216
#define PA_QK0 (2 * PA_TOK * PA_XSTRIDE)          // 18432
#define PA_QK1 (PA_QK0 + 16 * PA_QSTRIDE)
#define PA_SMEMF (PA_QK1 + 16 * PA_QSTRIDE)       // 19520 floats = 78080 B
#define NCH 24

__global__ __launch_bounds__(128) void pass_a(const float* __restrict__ X) {
    extern __shared__ float sm[];
    __shared__ float zs[16], ls[16];

    const int b   = blockIdx.y;
    const int s0  = blockIdx.x << 8;          // 256 tokens
    const int tid = threadIdx.x;
    const int sgrp = tid & 3;
    const int tgrp = tid >> 2;                // 0..31; tokens tgrp + 32*i, i<8

    const float* xbase = X + (size_t)(b * S_ + s0) * H_;
    const unsigned int smb = (unsigned int)__cvta_generic_to_shared(sm);

    if (tid < 16) { zs[tid] = 0.f; ls[tid] = 0.f; }

    float2 acc[8][4];
#pragma unroll
    for (int i = 0; i < 8; i++)
#pragma unroll
        for (int j = 0; j < 4; j++) acc[i][j] = make_float2(0.f, 0.f);

    // prefetch chunk 0 into buffer 0
    {
        const int hc = 0;
        unsigned int xd = smb + PA_XS0 * 4;
        unsigned int qd = smb + PA_QK0 * 4;
#pragma unroll
        for (int k = 0; k < 16; k++) {
            int idx = tid + (k << 7);                 // <2048
            int tok = idx >> 3, c4 = idx & 7;
            cp_async16(xd + (tok * PA_XSTRIDE + c4 * 4) * 4,
                       xbase + (size_t)tok * H_ + hc + c4 * 4);
        }
#pragma unroll
        for (int k = 0; k < 2; k++) {
            int idx = tid + (k << 7);                 // <256
            int n = idx >> 4, c2 = idx & 15;
            cp_async8(qd + (n * PA_QSTRIDE + c2 * 2) * 4,
                      g_qk + n * H_ + hc + c2 * 2);
        }
        CP_COMMIT();
    }

    for (int c = 0; c < NCH; c++) {
        if (c + 1 < NCH) {
            const int hc = (c + 1) << 5;
            const int nb = (c + 1) & 1;
            unsigned int xd = smb + (nb ? PA_XS1 : PA_XS0) * 4;
            unsigned int qd = smb + (nb ? PA_QK1 : PA_QK0) * 4;
#pragma unroll
            for (int k = 0; k < 16; k++) {
                int idx = tid + (k << 7);
                int tok = idx >> 3, c4 = idx & 7;
                cp_async16(xd + (tok * PA_XSTRIDE + c4 * 4) * 4,
                           xbase + (size_t)tok * H_ + hc + c4 * 4);
            }
#pragma unroll
            for (int k = 0; k < 2; k++) {
                int idx = tid + (k << 7);
                int n = idx >> 4, c2 = idx & 15;
                cp_async8(qd + (n * PA_QSTRIDE + c2 * 2) * 4,
                          g_qk + n * H_ + hc + c2 * 2);
            }
            CP_COMMIT();
            CP_WAIT(1);
        } else {
            CP_WAIT(0);
        }
        __syncthreads();

        const float* xs  = sm + ((c & 1) ? PA_XS1 : PA_XS0);
        const float* qks = sm + ((c & 1) ? PA_QK1 : PA_QK0);

#pragma unroll
        for (int h2 = 0; h2 < 16; h2++) {
            float2 qv[4];
#pragma unroll
            for (int j = 0; j < 4; j++)
                qv[j] = *(const float2*)&qks[(sgrp * 4 + j) * PA_QSTRIDE + h2 * 2];
#pragma unroll
            for (int i = 0; i < 8; i++) {
                float2 xv = *(const float2*)&xs[(tgrp + (i << 5)) * PA_XSTRIDE + h2 * 2];
#pragma unroll
                for (int j = 0; j < 4; j++) acc[i][j] = ffma2(xv, qv[j], acc[i][j]);
            }
        }
        __syncthreads();
    }

    float qb[4];
#pragma unroll
    for (int j = 0; j < 4; j++) qb[j] = g_qb[sgrp * 4 + j];

    float zp[4] = {0.f, 0.f, 0.f, 0.f}, lp[4] = {0.f, 0.f, 0.f, 0.f};
#pragma unroll
    for (int i = 0; i < 8; i++) {
        int s = s0 + tgrp + (i << 5);
#pragma unroll
        for (int j = 0; j < 4; j++) {
            int n = sgrp * 4 + j;
            float l = acc[i][j].x + acc[i][j].y + qb[j];
            float w = __expf(l);
            zp[j] += w;
            lp[j] += w * l;
            if (n < NS) g_w[((size_t)(b * NS + n)) * S_ + s] = w;
        }
    }
#pragma unroll
    for (int j = 0; j < 4; j++) {
        atomicAdd(&zs[sgrp * 4 + j], zp[j]);
        atomicAdd(&ls[sgrp * 4 + j], lp[j]);
    }
    __syncthreads();
    if (tid < 16) {
        atomicAdd(&g_Z[b * NP + tid], zs[tid]);
        atomicAdd(&g_L[b * NP + tid], ls[tid]);
    }
}

// ------------------------------------------------------------------
// pass B: g_T[b][n][h] += sum_s w*x via red.global.add.v4.
// grid (16 sc, 32 b), 192 thr. Thread owns h-float4 (tid*4).
// ------------------------------------------------------------------
__global__ __launch_bounds__(192) void pass_b(const float* __restrict__ X) {
    __shared__ float ws[2][NS * 64];

    const int sc  = blockIdx.x;
    const int b   = blockIdx.y;
    const int tid = threadIdx.x;
    const int sbeg = sc * 256;

    const unsigned int wsb = (unsigned int)__cvta_generic_to_shared(&ws[0][0]);
    const size_t wrow = (size_t)b * NS * S_;

    float2 acc[NS][2];
#pragma unroll
    for (int n = 0; n < NS; n++) { acc[n][0] = make_float2(0.f,0.f); acc[n][1] = make_float2(0.f,0.f); }

#pragma unroll
    for (int k = 0; k < 2; k++) {
        int idx = tid + k * 192;
        if (idx < NS * 16) {
            int n = idx >> 4, c4 = idx & 15;
            cp_async16(wsb + (n * 64 + c4 * 4) * 4,
                       g_w + wrow + (size_t)n * S_ + sbeg + c4 * 4);
        }
    }
    CP_COMMIT();

    const float* xp = X + (size_t)(b * S_ + sbeg) * H_ + tid * 4;

    for (int t = 0; t < 4; t++) {
        if (t + 1 < 4) {
            unsigned int dst = wsb + ((t + 1) & 1) * (NS * 64 * 4);
#pragma unroll
            for (int k = 0; k < 2; k++) {
                int idx = tid + k * 192;
                if (idx < NS * 16) {
                    int n = idx >> 4, c4 = idx & 15;
                    cp_async16(dst + (n * 64 + c4 * 4) * 4,
                               g_w + wrow + (size_t)n * S_ + sbeg + (t + 1) * 64 + c4 * 4);
                }
            }
            CP_COMMIT();
            CP_WAIT(1);
        } else {
            CP_WAIT(0);
        }
        __syncthreads();

        const float* wt = ws[t & 1];
#pragma unroll 2
        for (int sg = 0; sg < 64; sg += 4) {
            float4 xv[4];
#pragma unroll
            for (int u = 0; u < 4; u++) { xv[u] = *(const float4*)xp; xp += H_; }
#pragma unroll
            for (int n = 0; n < NS; n++) {
                float4 w4 = *(const float4*)&wt[n * 64 + sg];
                acc[n][0] = ffma2(make_float2(w4.x, w4.x), make_float2(xv[0].x, xv[0].y), acc[n][0]);
                acc[n][1] = ffma2(make_float2(w4.x, w4.x), make_float2(xv[0].z, xv[0].w), acc[n][1]);
                acc[n][0] = ffma2(make_float2(w4.y, w4.y), make_float2(xv[1].x, xv[1].y), acc[n][0]);
                acc[n][1] = ffma2(make_float2(w4.y, w4.y), make_float2(xv[1].z, xv[1].w), acc[n][1]);
                acc[n][0] = ffma2(make_float2(w4.z, w4.z), make_float2(xv[2].x, xv[2].y), acc[n][0]);
                acc[n][1] = ffma2(make_float2(w4.z, w4.z), make_float2(xv[2].z, xv[2].w), acc[n][1]);
                acc[n][0] = ffma2(make_float2(w4.w, w4.w), make_float2(xv[3].x, xv[3].y), acc[n][0]);
                acc[n][1] = ffma2(make_float2(w4.w, w4.w), make_float2(xv[3].z, xv[3].w), acc[n][1]);
            }
        }
        __syncthreads();
    }

#pragma unroll
    for (int n = 0; n < NS; n++) {
        red_add_v4(&g_T[(b * NS + n) * H_ + tid * 4],
                   acc[n][0].x, acc[n][0].y, acc[n][1].x, acc[n][1].y);
    }
}

// ------------------------------------------------------------------
// wv_kernel v2: se[b][n][d] = (g_T[b][n][:]/Z) @ Wv.
// grid (NS, 8), 384 thr = 4 h-quarters x 96 d-pairs; 4 batches/block.
// ------------------------------------------------------------------
__global__ __launch_bounds__(384) void wv_kernel(const float* __restrict__ Wv) {
    __shared__ float4 ts4[H_];              // [h] -> t for 4 batches
    __shared__ float invz[4];
    __shared__ float2 part[4][96][4];       // [hq][dp][b]
    const int n  = blockIdx.x;
    const int bg = blockIdx.y;              // batches bg*4..bg*4+3
    const int tid = threadIdx.x;

    if (tid < 4) invz[tid] = 1.0f / g_Z[(bg * 4 + tid) * NP + n];
    __syncthreads();

    // stage t (coalesced over h, one batch per 768-range)
#pragma unroll
    for (int k = 0; k < 8; k++) {
        int i = tid + k * 384;              // < 3072
        int bb = i / H_, hh = i - bb * H_;
        ((float*)&ts4[hh])[bb] =
            g_T[((bg * 4 + bb) * NS + n) * H_ + hh] * invz[bb];
    }
    __syncthreads();

    const int hq = tid / 96;                // 3 whole warps per quarter
    const int dp = tid - hq * 96;           // d-pair: d = 2*dp

    float2 a0 = make_float2(0.f,0.f), a1 = a0, a2 = a0, a3 = a0;
#pragma unroll 4
    for (int hh = 0; hh < 192; hh++) {
        int h = hq * 192 + hh;
        float2 wv2 = *(const float2*)(Wv + (size_t)h * D_ + 2 * dp);
        float4 tv = ts4[h];
        a0 = ffma2(wv2, make_float2(tv.x, tv.x), a0);
        a1 = ffma2(wv2, make_float2(tv.y, tv.y), a1);
        a2 = ffma2(wv2, make_float2(tv.z, tv.z), a2);
        a3 = ffma2(wv2, make_float2(tv.w, tv.w), a3);
    }
    part[hq][dp][0] = a0; part[hq][dp][1] = a1;
    part[hq][dp][2] = a2; part[hq][dp][3] = a3;
    __syncthreads();

    // reduce quarters: 384 threads cover 96 dp x 4 b
    {
        int dp2 = tid >> 2, b = tid & 3;
        float2 s0 = part[0][dp2][b], s1 = part[1][dp2][b];
        float2 s2 = part[2][dp2][b], s3 = part[3][dp2][b];
        float2 s = make_float2(s0.x + s1.x + s2.x + s3.x,
                               s0.y + s1.y + s2.y + s3.y);
        *(float2*)&g_sep[((bg * 4 + b) * NS + n) * D_ + 2 * dp2] = s;
    }
}

// ------------------------------------------------------------------
// R3: MLP head + strength. One block per batch (32 blocks, 256 thr).
// ------------------------------------------------------------------
#define R3_W1  0
#define R3_EFF 24576
#define R3_GH  (24576 + 15 * 384)
#define R3_SMEMF (R3_GH + 960)

__global__ __launch_bounds__(256) void r3_kernel(
    const float* __restrict__ bv, const float* __restrict__ NE,
    const float* __restrict__ W1, const float* __restrict__ b1,
    const float* __restrict__ W2, const float* __restrict__ b2,
    float* __restrict__ out) {
    extern __shared__ float sm[];
    float* W1s = sm + R3_W1;
    float* eff = sm + R3_EFF;   // [15][384]
    float* gh  = sm + R3_GH;    // [960]
    const int b = blockIdx.x, tid = threadIdx.x;

    {
        float4* d = (float4*)W1s;
        const float4* s = (const float4*)W1;
#pragma unroll
        for (int k = 0; k < 24; k++) d[tid + 256 * k] = s[tid + 256 * k];
    }
    for (int i = tid; i < NS * 384; i += 256) {
        int n = i / 384, ii = i - n * 384;
        float v;
        if (ii < D_) v = bv[ii] + g_sep[(b * NS + n) * D_ + ii];
        else         v = NE[(size_t)n * H_ + (ii - D_)];
        eff[i] = v;
    }
    __syncthreads();

#pragma unroll
    for (int k = 0; k < 4; k++) {
        int u = tid + 256 * k;
        if (u < NS * 64) {
            int n = u >> 6, j = u & 63;
            const float* e = eff + n * 384;
            float h = b1[j];
#pragma unroll 4
            for (int i = 0; i < 384; i++) h = fmaf(e[i], W1s[i * 64 + j], h);
            gh[u] = 0.5f * h * (1.0f + erff(h * 0.70710678118654752f));
        }
    }
    if (tid < NS) {
        float Z = g_Z[b * NP + tid], L = g_L[b * NP + tid];
        float ent = logf(Z) - L / Z;
        out[b * (2 * NS) + NS + tid] = 1.0f - ent * (1.0f / LOG_S);
    }
    __syncthreads();

    int wid = tid >> 5, lid = tid & 31;
#pragma unroll
    for (int r = 0; r < 2; r++) {
        int n = wid * 2 + r;
        if (n < NS) {
            float v = gh[n * 64 + lid] * W2[lid] + gh[n * 64 + lid + 32] * W2[lid + 32];
#pragma unroll
            for (int o = 16; o; o >>= 1) v += __shfl_xor_sync(0xffffffffu, v, o);
            if (lid == 0) out[b * (2 * NS) + n] = v + b2[0];
        }
    }
}

// ------------------------------------------------------------------
extern "C" void kernel_launch(void* const* d_in, const int* in_sizes, int n_in,
                              void* d_out, int out_size) {
    const float* X   = (const float*)d_in[0];
    const float* Wk  = (const float*)d_in[1];
    const float* bk  = (const float*)d_in[2];
    const float* Wv  = (const float*)d_in[3];
    const float* bv  = (const float*)d_in[4];
    const float* SQ  = (const float*)d_in[5];
    const float* NE  = (const float*)d_in[6];
    const float* W1  = (const float*)d_in[7];
    const float* b1  = (const float*)d_in[8];
    const float* W2  = (const float*)d_in[9];
    const float* b2  = (const float*)d_in[10];
    float* out = (float*)d_out;                 // [32,30]

    cudaFuncSetAttribute(pass_a, cudaFuncAttributeMaxDynamicSharedMemorySize,
                         PA_SMEMF * 4);
    cudaFuncSetAttribute(r3_kernel, cudaFuncAttributeMaxDynamicSharedMemorySize,
                         R3_SMEMF * 4);

    prep_kernel<<<48, 256>>>(SQ, Wk, bk);
    pass_a<<<dim3(16, B_), 128, PA_SMEMF * 4>>>(X);
    pass_b<<<dim3(SCB, B_), 192>>>(X);
    wv_kernel<<<dim3(NS, 8), 384>>>(Wv);
    r3_kernel<<<B_, 256, R3_SMEMF * 4>>>(bv, NE, W1, b1, W2, b2, out);
}

// round 9
// speedup vs baseline: 2.1238x; 1.1259x over previous
#include <cuda_runtime.h>
#include <stdint.h>
#include <math.h>

#define B_   32
#define S_   4096
#define H_   768
#define D_   192
#define NS   15
#define NP   16

#define INV_SCALE 0.072168783648703220563f   // 1/sqrt(192)
#define LOG_S     8.3177661667193433f        // log(4096)

// ------------------------------------------------------------------
// device scratch
// ------------------------------------------------------------------
__device__ float g_qk[NP * H_];                 // folded queries (scaled)
__device__ float g_qb[NP];
__device__ float g_Z[B_ * NP];
__device__ float g_L[B_ * NP];
__device__ float g_w[(size_t)B_ * NS * S_];     // exp(logit)
__device__ float g_T[B_ * NS * H_];             // dense weighted-x sums (red.add)
__device__ float g_sep[B_ * NS * D_];           // signal embeds (pre-bias)

// packed f32x2 FMA
__device__ __forceinline__ float2 ffma2(float2 a, float2 b, float2 c) {
    float2 d;
    asm("fma.rn.f32x2 %0, %1, %2, %3;"
        : "=l"(reinterpret_cast<unsigned long long&>(d))
        : "l"(reinterpret_cast<unsigned long long&>(a)),
          "l"(reinterpret_cast<unsigned long long&>(b)),
          "l"(reinterpret_cast<unsigned long long&>(c)));
    return d;
}

__device__ __forceinline__ void cp_async16(unsigned int saddr, const void* gaddr) {
    asm volatile("cp.async.cg.shared.global [%0], [%1], 16;" :: "r"(saddr), "l"(gaddr));
}
__device__ __forceinline__ void cp_async8(unsigned int saddr, const void* gaddr) {
    asm volatile("cp.async.ca.shared.global [%0], [%1], 8;" :: "r"(saddr), "l"(gaddr));
}
#define CP_COMMIT()  asm volatile("cp.async.commit_group;")
#define CP_WAIT(N)   asm volatile("cp.async.wait_group %0;" :: "n"(N))

__device__ __forceinline__ void red_add_v2(float* ptr, float a, float b) {
    asm volatile("red.global.add.v2.f32 [%0], {%1,%2};"
                 :: "l"(ptr), "f"(a), "f"(b) : "memory");
}

// ------------------------------------------------------------------
// prep: g_qk = (Wk @ q_n)/sqrt(d), g_qb; zero Z/L and g_T
// ------------------------------------------------------------------
__global__ void prep_kernel(const float* __restrict__ SQ,
                            const float* __restrict__ Wk,
                            const float* __restrict__ bk) {
    int idx = blockIdx.x * 256 + threadIdx.x;   // 0..12287
    int h = idx >> 4, n = idx & 15;
    float v = 0.f;
    if (n < NS) {
        float s = 0.f;
        const float* q = SQ + n * D_;
        const float* w = Wk + h * D_;
#pragma unroll 8
        for (int d = 0; d < D_; d++) s += q[d] * w[d];
        v = s * INV_SCALE;
    }
    g_qk[n * H_ + h] = v;
    if (idx < NP) {
        float s = 0.f;
        if (idx < NS) {
            const float* q = SQ + idx * D_;
            for (int d = 0; d < D_; d++) s += q[d] * bk[d];
        }
        g_qb[idx] = s * INV_SCALE;
    }
    if (idx < B_ * NP) { g_Z[idx] = 0.f; g_L[idx] = 0.f; }
#pragma unroll
    for (int k = 0; k < 30; k++)            // 30*12288 = B*NS*H
        g_T[idx + k * 12288] = 0.f;
}

// ------------------------------------------------------------------
// pass A: logits + exp + Z/L. grid (32 schunks, 32 b), 128 thr.
// 128 tokens/block, h in 32-chunks, cp.async double-buffered.
// Thread tile: 4 tok x 4 sig. smem 41216 B -> 5 CTAs/SM (20 warps).
// ------------------------------------------------------------------
#define PA_XSTRIDE 36
#define PA_QSTRIDE 34
#define PA_XS0 0
#define PA_XS1 (128 * PA_XSTRIDE)
#define PA_QK0 (2 * 128 * PA_XSTRIDE)
#define PA_QK1 (PA_QK0 + 16 * PA_QSTRIDE)
#define PA_SMEMF (PA_QK1 + 16 * PA_QSTRIDE)
#define NCH 24

__global__ __launch_bounds__(128) void pass_a(const float* __restrict__ X) {
    extern __shared__ float sm[];
    __shared__ float zs[16], ls[16];

    const int b   = blockIdx.y;
    const int s0  = blockIdx.x << 7;
    const int tid = threadIdx.x;
    const int sgrp = tid & 3;
    const int tgrp = tid >> 2;

    const float* xbase = X + (size_t)(b * S_ + s0) * H_;
    const unsigned int smb = (unsigned int)__cvta_generic_to_shared(sm);

    if (tid < 16) { zs[tid] = 0.f; ls[tid] = 0.f; }

    float2 acc[4][4];
#pragma unroll
    for (int i = 0; i < 4; i++)
#pragma unroll
        for (int j = 0; j < 4; j++) acc[i][j] = make_float2(0.f, 0.f);

    {
        const int hc = 0;
        unsigned int xd = smb + PA_XS0 * 4;
        unsigned int qd = smb + PA_QK0 * 4;
#pragma unroll
        for (int k = 0; k < 8; k++) {
            int idx = tid + (k << 7);
            int tok = idx >> 3, c4 = idx & 7;
            cp_async16(xd + (tok * PA_XSTRIDE + c4 * 4) * 4,
                       xbase + (size_t)tok * H_ + hc + c4 * 4);
        }
#pragma unroll
        for (int k = 0; k < 2; k++) {
            int idx = tid + (k << 7);
            int n = idx >> 4, c2 = idx & 15;
            cp_async8(qd + (n * PA_QSTRIDE + c2 * 2) * 4,
                      g_qk + n * H_ + hc + c2 * 2);
        }
        CP_COMMIT();
    }

    for (int c = 0; c < NCH; c++) {
        if (c + 1 < NCH) {
            const int hc = (c + 1) << 5;
            const int nb = (c + 1) & 1;
            unsigned int xd = smb + (nb ? PA_XS1 : PA_XS0) * 4;
            unsigned int qd = smb + (nb ? PA_QK1 : PA_QK0) * 4;
#pragma unroll
            for (int k = 0; k < 8; k++) {
                int idx = tid + (k << 7);
                int tok = idx >> 3, c4 = idx & 7;
                cp_async16(xd + (tok * PA_XSTRIDE + c4 * 4) * 4,
                           xbase + (size_t)tok * H_ + hc + c4 * 4);
            }
#pragma unroll
            for (int k = 0; k < 2; k++) {
                int idx = tid + (k << 7);
                int n = idx >> 4, c2 = idx & 15;
                cp_async8(qd + (n * PA_QSTRIDE + c2 * 2) * 4,
                          g_qk + n * H_ + hc + c2 * 2);
            }
            CP_COMMIT();
            CP_WAIT(1);
        } else {
            CP_WAIT(0);
        }
        __syncthreads();

        const float* xs  = sm + ((c & 1) ? PA_XS1 : PA_XS0);
        const float* qks = sm + ((c & 1) ? PA_QK1 : PA_QK0);

#pragma unroll
        for (int h2 = 0; h2 < 16; h2++) {
            float2 qv[4];
#pragma unroll
            for (int j = 0; j < 4; j++)
                qv[j] = *(const float2*)&qks[(sgrp * 4 + j) * PA_QSTRIDE + h2 * 2];
#pragma unroll
            for (int i = 0; i < 4; i++) {
                float2 xv = *(const float2*)&xs[(tgrp + (i << 5)) * PA_XSTRIDE + h2 * 2];
#pragma unroll
                for (int j = 0; j < 4; j++) acc[i][j] = ffma2(xv, qv[j], acc[i][j]);
            }
        }
        __syncthreads();
    }

    float qb[4];
#pragma unroll
    for (int j = 0; j < 4; j++) qb[j] = g_qb[sgrp * 4 + j];

    float zp[4] = {0.f, 0.f, 0.f, 0.f}, lp[4] = {0.f, 0.f, 0.f, 0.f};
#pragma unroll
    for (int i = 0; i < 4; i++) {
        int s = s0 + tgrp + (i << 5);
#pragma unroll
        for (int j = 0; j < 4; j++) {
            int n = sgrp * 4 + j;
            float l = acc[i][j].x + acc[i][j].y + qb[j];
            float w = __expf(l);
            zp[j] += w;
            lp[j] += w * l;
            if (n < NS) g_w[((size_t)(b * NS + n)) * S_ + s] = w;
        }
    }
#pragma unroll
    for (int j = 0; j < 4; j++) {
        atomicAdd(&zs[sgrp * 4 + j], zp[j]);
        atomicAdd(&ls[sgrp * 4 + j], lp[j]);
    }
    __syncthreads();
    if (tid < 16) {
        atomicAdd(&g_Z[b * NP + tid], zs[tid]);
        atomicAdd(&g_L[b * NP + tid], ls[tid]);
    }
}

// ------------------------------------------------------------------
// pass B v3: g_T[b][n][h] += sum_s w*x via red.global.add.v2.
// grid (8 sc, 2 hc, 32 b) = 1024 blocks, 192 thr.
// Thread owns h-float2 (hc*384 + tid*2); 30 acc regs -> high occupancy.
// w tiles of 128 tokens, cp.async double-buffered.
// ------------------------------------------------------------------
__global__ __launch_bounds__(192) void pass_b(const float* __restrict__ X) {
    __shared__ float ws[2][NS * 128];

    const int sc  = blockIdx.x;           // 0..7 (512 tokens each)
    const int hc  = blockIdx.y;           // 0..1
    const int b   = blockIdx.z;
    const int tid = threadIdx.x;
    const int sbeg = sc * 512;
    const int hoff = hc * 384 + tid * 2;

    const unsigned int wsb = (unsigned int)__cvta_generic_to_shared(&ws[0][0]);
    const size_t wrow = (size_t)b * NS * S_;

    float2 acc[NS];
#pragma unroll
    for (int n = 0; n < NS; n++) acc[n] = make_float2(0.f, 0.f);

    // prefetch w tile 0 (NS*128 floats = 480 float4)
#pragma unroll
    for (int k = 0; k < 3; k++) {
        int idx = tid + k * 192;
        if (idx < NS * 32) {
            int n = idx >> 5, c4 = idx & 31;
            cp_async16(wsb + (n * 128 + c4 * 4) * 4,
                       g_w + wrow + (size_t)n * S_ + sbeg + c4 * 4);
        }
    }
    CP_COMMIT();

    const float* xp = X + (size_t)(b * S_ + sbeg) * H_ + hoff;

    for (int t = 0; t < 4; t++) {
        if (t + 1 < 4) {
            unsigned int dst = wsb + ((t + 1) & 1) * (NS * 128 * 4);
#pragma unroll
            for (int k = 0; k < 3; k++) {
                int idx = tid + k * 192;
                if (idx < NS * 32) {
                    int n = idx >> 5, c4 = idx & 31;
                    cp_async16(dst + (n * 128 + c4 * 4) * 4,
                               g_w + wrow + (size_t)n * S_ + sbeg + (t + 1) * 128 + c4 * 4);
                }
            }
            CP_COMMIT();
            CP_WAIT(1);
        } else {
            CP_WAIT(0);
        }
        __syncthreads();

        const float* wt = ws[t & 1];
#pragma unroll 2
        for (int sg = 0; sg < 128; sg += 4) {
            float2 xv[4];
#pragma unroll
            for (int u = 0; u < 4; u++)
                xv[u] = *(const float2*)(xp + (size_t)(sg + u) * H_);
#pragma unroll
            for (int n = 0; n < NS; n++) {
                float4 w4 = *(const float4*)&wt[n * 128 + sg];
                acc[n] = ffma2(make_float2(w4.x, w4.x), xv[0], acc[n]);
                acc[n] = ffma2(make_float2(w4.y, w4.y), xv[1], acc[n]);
                acc[n] = ffma2(make_float2(w4.z, w4.z), xv[2], acc[n]);
                acc[n] = ffma2(make_float2(w4.w, w4.w), xv[3], acc[n]);
            }
        }
        xp += (size_t)128 * H_;
        __syncthreads();
    }

#pragma unroll
    for (int n = 0; n < NS; n++)
        red_add_v2(&g_T[(b * NS + n) * H_ + hoff], acc[n].x, acc[n].y);
}

// ------------------------------------------------------------------
// wv_kernel: se[b][n][d] = (g_T[b][n][:]/Z) @ Wv.
// grid (NS, 8), 384 thr = 4 h-quarters x 96 d-pairs; 4 batches/block.
// ------------------------------------------------------------------
__global__ __launch_bounds__(384) void wv_kernel(const float* __restrict__ Wv) {
    __shared__ float4 ts4[H_];              // [h] -> t for 4 batches
    __shared__ float invz[4];
    __shared__ float2 part[4][96][4];       // [hq][dp][b]
    const int n  = blockIdx.x;
    const int bg = blockIdx.y;
    const int tid = threadIdx.x;

    if (tid < 4) invz[tid] = 1.0f / g_Z[(bg * 4 + tid) * NP + n];
    __syncthreads();

#pragma unroll
    for (int k = 0; k < 8; k++) {
        int i = tid + k * 384;
        int bb = i / H_, hh = i - bb * H_;
        ((float*)&ts4[hh])[bb] =
            g_T[((bg * 4 + bb) * NS + n) * H_ + hh] * invz[bb];
    }
    __syncthreads();

    const int hq = tid / 96;
    const int dp = tid - hq * 96;

    float2 a0 = make_float2(0.f,0.f), a1 = a0, a2 = a0, a3 = a0;
#pragma unroll 4
    for (int hh = 0; hh < 192; hh++) {
        int h = hq * 192 + hh;
        float2 wv2 = *(const float2*)(Wv + (size_t)h * D_ + 2 * dp);
        float4 tv = ts4[h];
        a0 = ffma2(wv2, make_float2(tv.x, tv.x), a0);
        a1 = ffma2(wv2, make_float2(tv.y, tv.y), a1);
        a2 = ffma2(wv2, make_float2(tv.z, tv.z), a2);
        a3 = ffma2(wv2, make_float2(tv.w, tv.w), a3);
    }
    part[hq][dp][0] = a0; part[hq][dp][1] = a1;
    part[hq][dp][2] = a2; part[hq][dp][3] = a3;
    __syncthreads();

    {
        int dp2 = tid >> 2, b = tid & 3;
        float2 s0 = part[0][dp2][b], s1 = part[1][dp2][b];
        float2 s2 = part[2][dp2][b], s3 = part[3][dp2][b];
        float2 s = make_float2(s0.x + s1.x + s2.x + s3.x,
                               s0.y + s1.y + s2.y + s3.y);
        *(float2*)&g_sep[((bg * 4 + b) * NS + n) * D_ + 2 * dp2] = s;
    }
}

// ------------------------------------------------------------------
// R3: MLP head + strength. One block per batch (32 blocks, 256 thr).
// ------------------------------------------------------------------
#define R3_W1  0
#define R3_EFF 24576
#define R3_GH  (24576 + 15 * 384)
#define R3_SMEMF (R3_GH + 960)

__global__ __launch_bounds__(256) void r3_kernel(
    const float* __restrict__ bv, const float* __restrict__ NE,
    const float* __restrict__ W1, const float* __restrict__ b1,
    const float* __restrict__ W2, const float* __restrict__ b2,
    float* __restrict__ out) {
    extern __shared__ float sm[];
    float* W1s = sm + R3_W1;
    float* eff = sm + R3_EFF;   // [15][384]
    float* gh  = sm + R3_GH;    // [960]
    const int b = blockIdx.x, tid = threadIdx.x;

    {
        float4* d = (float4*)W1s;
        const float4* s = (const float4*)W1;
#pragma unroll
        for (int k = 0; k < 24; k++) d[tid + 256 * k] = s[tid + 256 * k];
    }
    for (int i = tid; i < NS * 384; i += 256) {
        int n = i / 384, ii = i - n * 384;
        float v;
        if (ii < D_) v = bv[ii] + g_sep[(b * NS + n) * D_ + ii];
        else         v = NE[(size_t)n * H_ + (ii - D_)];
        eff[i] = v;
    }
    __syncthreads();

#pragma unroll
    for (int k = 0; k < 4; k++) {
        int u = tid + 256 * k;
        if (u < NS * 64) {
            int n = u >> 6, j = u & 63;
            const float* e = eff + n * 384;
            float h0 = b1[j], h1 = 0.f;          // 2-way ILP
#pragma unroll 4
            for (int i = 0; i < 384; i += 2) {
                h0 = fmaf(e[i],     W1s[i * 64 + j],       h0);
                h1 = fmaf(e[i + 1], W1s[(i + 1) * 64 + j], h1);
            }
            float h = h0 + h1;
            gh[u] = 0.5f * h * (1.0f + erff(h * 0.70710678118654752f));
        }
    }
    if (tid < NS) {
        float Z = g_Z[b * NP + tid], L = g_L[b * NP + tid];
        float ent = logf(Z) - L / Z;
        out[b * (2 * NS) + NS + tid] = 1.0f - ent * (1.0f / LOG_S);
    }
    __syncthreads();

    int wid = tid >> 5, lid = tid & 31;
#pragma unroll
    for (int r = 0; r < 2; r++) {
        int n = wid * 2 + r;
        if (n < NS) {
            float v = gh[n * 64 + lid] * W2[lid] + gh[n * 64 + lid + 32] * W2[lid + 32];
#pragma unroll
            for (int o = 16; o; o >>= 1) v += __shfl_xor_sync(0xffffffffu, v, o);
            if (lid == 0) out[b * (2 * NS) + n] = v + b2[0];
        }
    }
}

// ------------------------------------------------------------------
extern "C" void kernel_launch(void* const* d_in, const int* in_sizes, int n_in,
                              void* d_out, int out_size) {
    const float* X   = (const float*)d_in[0];
    const float* Wk  = (const float*)d_in[1];
    const float* bk  = (const float*)d_in[2];
    const float* Wv  = (const float*)d_in[3];
    const float* bv  = (const float*)d_in[4];
    const float* SQ  = (const float*)d_in[5];
    const float* NE  = (const float*)d_in[6];
    const float* W1  = (const float*)d_in[7];
    const float* b1  = (const float*)d_in[8];
    const float* W2  = (const float*)d_in[9];
    const float* b2  = (const float*)d_in[10];
    float* out = (float*)d_out;                 // [32,30]

    cudaFuncSetAttribute(pass_a, cudaFuncAttributeMaxDynamicSharedMemorySize,
                         PA_SMEMF * 4);
    cudaFuncSetAttribute(r3_kernel, cudaFuncAttributeMaxDynamicSharedMemorySize,
                         R3_SMEMF * 4);

    prep_kernel<<<48, 256>>>(SQ, Wk, bk);
    pass_a<<<dim3(32, B_), 128, PA_SMEMF * 4>>>(X);
    pass_b<<<dim3(8, 2, B_), 192>>>(X);
    wv_kernel<<<dim3(NS, 8), 384>>>(Wv);
    r3_kernel<<<B_, 256, R3_SMEMF * 4>>>(bv, NE, W1, b1, W2, b2, out);
}